// round 2
// baseline (speedup 1.0000x reference)
#include <cuda_runtime.h>
#include <math.h>
#include <stdint.h>

#define DEPTH_  4
#define DIM_    1024
#define HEADS_  16
#define DHEAD_  64
#define MLP_    4096
#define CTX_    1024
#define INNER_  1024          // HEADS_*DHEAD_
#define B_      4
#define N_      1024
#define M_      2048
#define SCALE_  0.125f        // 64^-0.5

#define FLAG_RES  1
#define FLAG_GELU 2

// ---------------- scratch (static device globals; no allocs allowed) ----------------
__device__ float g_h      [B_ * N_ * DIM_];                       // 16 MB
__device__ float g_qkv    [B_ * N_ * 3 * INNER_];                 // 48 MB
__device__ float g_kv     [B_ * M_ * 2 * INNER_];                 // 64 MB
__device__ float g_q      [B_ * N_ * INNER_];                     // 16 MB
__device__ float g_scores [(size_t)B_ * HEADS_ * N_ * M_];        // 512 MB (covers SA N*N too)
__device__ float g_attnout[B_ * N_ * INNER_];                     // 16 MB
__device__ float g_ffn    [B_ * N_ * MLP_];                       // 64 MB

// ---------------- reductions ----------------
__device__ __forceinline__ float warpSum(float v) {
    #pragma unroll
    for (int o = 16; o; o >>= 1) v += __shfl_xor_sync(0xffffffffu, v, o);
    return v;
}
__device__ __forceinline__ float warpMax(float v) {
    #pragma unroll
    for (int o = 16; o; o >>= 1) v = fmaxf(v, __shfl_xor_sync(0xffffffffu, v, o));
    return v;
}

// ---------------- LayerNorm: one block per row, DIM_=1024, 256 threads ----------------
__global__ __launch_bounds__(256) void ln_kernel(
    const float* __restrict__ x, const float* __restrict__ g,
    const float* __restrict__ b, float* __restrict__ o)
{
    const int row = blockIdx.x;
    const float* xr = x + (size_t)row * DIM_;
    float* orow = o + (size_t)row * DIM_;

    float v[4];
    float s = 0.f, ss = 0.f;
    #pragma unroll
    for (int i = 0; i < 4; i++) {
        v[i] = xr[threadIdx.x + i * 256];
        s += v[i]; ss += v[i] * v[i];
    }
    __shared__ float shs[8], shq[8];
    float ws = warpSum(s), wq = warpSum(ss);
    int wid = threadIdx.x >> 5, lane = threadIdx.x & 31;
    if (lane == 0) { shs[wid] = ws; shq[wid] = wq; }
    __syncthreads();
    if (threadIdx.x == 0) {
        float a = 0.f, c = 0.f;
        #pragma unroll
        for (int w = 0; w < 8; w++) { a += shs[w]; c += shq[w]; }
        shs[0] = a; shq[0] = c;
    }
    __syncthreads();
    const float mean = shs[0] * (1.f / DIM_);
    const float var  = shq[0] * (1.f / DIM_) - mean * mean;
    const float rstd = rsqrtf(var + 1e-5f);
    #pragma unroll
    for (int i = 0; i < 4; i++) {
        int c = threadIdx.x + i * 256;
        orow[c] = (v[i] - mean) * rstd * g[c] + b[c];
    }
}

// ---------------- softmax over rows (nk = 1024 or 2048), 256 threads ----------------
// mask (optional): per-key mask, index mask[b*nk + m]; logit -= (1-mask)*mbias
__global__ __launch_bounds__(256) void softmax_kernel(
    float* __restrict__ S, int nk, int rows_per_b,
    const int* __restrict__ mask, float mbias)
{
    const size_t row = blockIdx.x;
    float* r = S + row * (size_t)nk;
    const int* mrow = mask ? (mask + (size_t)(row / rows_per_b) * nk) : nullptr;
    const int cnt = nk >> 8;                 // 4 or 8

    float v[8];
    float mx = -3.4e38f;
    #pragma unroll 8
    for (int i = 0; i < 8; i++) {
        if (i < cnt) {
            int c = (i << 8) + threadIdx.x;
            float val = r[c];
            if (mrow) val -= (1.f - (float)mrow[c]) * mbias;
            v[i] = val;
            mx = fmaxf(mx, val);
        }
    }
    __shared__ float shm[8], shs[8];
    int wid = threadIdx.x >> 5, lane = threadIdx.x & 31;
    float wm = warpMax(mx);
    if (lane == 0) shm[wid] = wm;
    __syncthreads();
    if (threadIdx.x == 0) {
        float m = shm[0];
        #pragma unroll
        for (int w = 1; w < 8; w++) m = fmaxf(m, shm[w]);
        shm[0] = m;
    }
    __syncthreads();
    mx = shm[0];

    float sum = 0.f;
    #pragma unroll 8
    for (int i = 0; i < 8; i++) {
        if (i < cnt) { v[i] = expf(v[i] - mx); sum += v[i]; }
    }
    float wsm = warpSum(sum);
    if (lane == 0) shs[wid] = wsm;
    __syncthreads();
    if (threadIdx.x == 0) {
        float a = 0.f;
        #pragma unroll
        for (int w = 0; w < 8; w++) a += shs[w];
        shs[0] = a;
    }
    __syncthreads();
    const float inv = 1.f / shs[0];
    #pragma unroll 8
    for (int i = 0; i < 8; i++) {
        if (i < cnt) r[(i << 8) + threadIdx.x] = v[i] * inv;
    }
}

// ---------------- generic strided-batched SGEMM ----------------
// C[bh] = alpha * A[bh] (MxK) * op(B[bh]) + bias + (residual?) ; op = B (KxN) or B^T (NxK)
// batch index z -> b = z/HEADS_, h = z%HEADS_; per-operand offsets b*s?b + h*s?h
#define BM 128
#define BN 128
#define BKK 16

template<bool TB>
__global__ __launch_bounds__(256) void gemm_kernel(
    const float* __restrict__ A, int lda, long sAb, long sAh,
    const float* __restrict__ Bp, int ldb, long sBb, long sBh,
    float* __restrict__ C, int ldc, long sCb, long sCh,
    int Mdim, int Ndim, int Kdim, float alpha,
    const float* __restrict__ bias, int flags)
{
    __shared__ float As[BKK][BM];
    __shared__ float Bs[BKK][BN];

    const int z = blockIdx.z;
    const int bb = z / HEADS_, hh = z % HEADS_;
    A  += (size_t)bb * sAb + (size_t)hh * sAh;
    Bp += (size_t)bb * sBb + (size_t)hh * sBh;
    C  += (size_t)bb * sCb + (size_t)hh * sCh;

    const int rowBase = blockIdx.y * BM;
    const int colBase = blockIdx.x * BN;
    const int tid = threadIdx.x;
    const int tx = tid & 15, ty = tid >> 4;

    float acc[8][8];
    #pragma unroll
    for (int i = 0; i < 8; i++)
        #pragma unroll
        for (int j = 0; j < 8; j++) acc[i][j] = 0.f;

    for (int k0 = 0; k0 < Kdim; k0 += BKK) {
        // ---- load A tile: BM x BKK (A row-major, M always multiple of 128, K of 16)
        #pragma unroll
        for (int it = 0; it < 2; it++) {
            int l = tid + it * 256;          // 0..511
            int ar = l >> 2;                 // 0..127
            int ac = (l & 3) * 4;            // 0,4,8,12
            float4 va = *(const float4*)(A + (size_t)(rowBase + ar) * lda + k0 + ac);
            As[ac + 0][ar] = va.x; As[ac + 1][ar] = va.y;
            As[ac + 2][ar] = va.z; As[ac + 3][ar] = va.w;
        }
        // ---- load B tile
        if (!TB) {
            #pragma unroll
            for (int it = 0; it < 2; it++) {
                int l = tid + it * 256;
                int br = l >> 5;             // 0..15
                int bc = (l & 31) * 4;       // 0..124
                int gc = colBase + bc;
                float4 vb;
                if (gc < Ndim) vb = *(const float4*)(Bp + (size_t)(k0 + br) * ldb + gc);
                else vb = make_float4(0.f, 0.f, 0.f, 0.f);
                *(float4*)&Bs[br][bc] = vb;
            }
        } else {
            // Bs[k][n] = Bp[colBase+n][k0+k]  (keys x dhead, contiguous along k)
            #pragma unroll
            for (int it = 0; it < 2; it++) {
                int l = tid + it * 256;
                int n  = l >> 2;             // 0..127
                int kc = (l & 3) * 4;        // 0,4,8,12
                float4 vb = *(const float4*)(Bp + (size_t)(colBase + n) * ldb + k0 + kc);
                Bs[kc + 0][n] = vb.x; Bs[kc + 1][n] = vb.y;
                Bs[kc + 2][n] = vb.z; Bs[kc + 3][n] = vb.w;
            }
        }
        __syncthreads();

        #pragma unroll
        for (int kk = 0; kk < BKK; kk++) {
            float a[8], b[8];
            *(float4*)&a[0] = *(const float4*)&As[kk][ty * 8];
            *(float4*)&a[4] = *(const float4*)&As[kk][ty * 8 + 4];
            *(float4*)&b[0] = *(const float4*)&Bs[kk][tx * 8];
            *(float4*)&b[4] = *(const float4*)&Bs[kk][tx * 8 + 4];
            #pragma unroll
            for (int i = 0; i < 8; i++)
                #pragma unroll
                for (int j = 0; j < 8; j++)
                    acc[i][j] = fmaf(a[i], b[j], acc[i][j]);
        }
        __syncthreads();
    }

    // ---- epilogue
    #pragma unroll
    for (int i = 0; i < 8; i++) {
        int r = rowBase + ty * 8 + i;
        if (r >= Mdim) continue;
        #pragma unroll
        for (int j = 0; j < 8; j++) {
            int c = colBase + tx * 8 + j;
            if (c >= Ndim) continue;
            float v = alpha * acc[i][j];
            if (bias) v += bias[c];
            if (flags & FLAG_GELU) v = 0.5f * v * (1.f + erff(v * 0.70710678118654752f));
            float* cp = C + (size_t)r * ldc + c;
            if (flags & FLAG_RES) v += *cp;
            *cp = v;
        }
    }
}

// ---------------- host-side launch helpers ----------------
static void gemm(bool tb,
                 const float* A, int lda, long sAb, long sAh,
                 const float* Bp, int ldb, long sBb, long sBh,
                 float* C, int ldc, long sCb, long sCh,
                 int M, int N, int K, float alpha,
                 const float* bias, int flags, int batches)
{
    dim3 grid((N + BN - 1) / BN, (M + BM - 1) / BM, batches);
    if (tb)
        gemm_kernel<true><<<grid, 256>>>(A, lda, sAb, sAh, Bp, ldb, sBb, sBh,
                                         C, ldc, sCb, sCh, M, N, K, alpha, bias, flags);
    else
        gemm_kernel<false><<<grid, 256>>>(A, lda, sAb, sAh, Bp, ldb, sBb, sBh,
                                          C, ldc, sCb, sCh, M, N, K, alpha, bias, flags);
}

extern "C" void kernel_launch(void* const* d_in, const int* in_sizes, int n_in,
                              void* d_out, int out_size)
{
    const float* x       = (const float*)d_in[0];
    const float* context = (const float*)d_in[1];
    const int*   mask    = (const int*)  d_in[2];
    const float* ln_g    = (const float*)d_in[3];
    const float* ln_b    = (const float*)d_in[4];
    const float* Wqkv    = (const float*)d_in[5];
    const float* Wo_sa   = (const float*)d_in[6];
    const float* bo_sa   = (const float*)d_in[7];
    const float* Wkv     = (const float*)d_in[8];
    const float* Wq      = (const float*)d_in[9];
    const float* Wo_ca   = (const float*)d_in[10];
    const float* bo_ca   = (const float*)d_in[11];
    const float* W1      = (const float*)d_in[12];
    const float* b1      = (const float*)d_in[13];
    const float* W2      = (const float*)d_in[14];
    const float* b2      = (const float*)d_in[15];
    float* xout = (float*)d_out;

    float *h, *qkv, *kv, *q, *scores, *attnout, *ffn;
    cudaGetSymbolAddress((void**)&h,       g_h);
    cudaGetSymbolAddress((void**)&qkv,     g_qkv);
    cudaGetSymbolAddress((void**)&kv,      g_kv);
    cudaGetSymbolAddress((void**)&q,       g_q);
    cudaGetSymbolAddress((void**)&scores,  g_scores);
    cudaGetSymbolAddress((void**)&attnout, g_attnout);
    cudaGetSymbolAddress((void**)&ffn,     g_ffn);

    // residual stream lives in d_out
    cudaMemcpyAsync(xout, x, sizeof(float) * B_ * N_ * DIM_, cudaMemcpyDeviceToDevice, 0);

    const int BH = B_ * HEADS_;

    for (int i = 0; i < DEPTH_; i++) {
        // ================= self-attention =================
        ln_kernel<<<B_ * N_, 256>>>(xout, ln_g + (size_t)(i * 3 + 0) * DIM_,
                                    ln_b + (size_t)(i * 3 + 0) * DIM_, h);
        // qkv = h @ Wqkv[i]      [4096 x 3072]
        gemm(false, h, DIM_, 0, 0,
             Wqkv + (size_t)i * DIM_ * 3 * INNER_, 3 * INNER_, 0, 0,
             qkv, 3 * INNER_, 0, 0,
             B_ * N_, 3 * INNER_, DIM_, 1.f, nullptr, 0, 1);
        // scores = Q K^T * scale   per (b,h): [1024 x 1024], K-dim 64
        gemm(true, qkv, 3 * INNER_, (long)N_ * 3 * INNER_, DHEAD_,
             qkv + INNER_, 3 * INNER_, (long)N_ * 3 * INNER_, DHEAD_,
             scores, N_, (long)HEADS_ * N_ * N_, (long)N_ * N_,
             N_, N_, DHEAD_, SCALE_, nullptr, 0, BH);
        softmax_kernel<<<BH * N_, 256>>>(scores, N_, HEADS_ * N_, mask, 1e11f);
        // out = attn @ V           per (b,h): [1024 x 64], K-dim 1024
        gemm(false, scores, N_, (long)HEADS_ * N_ * N_, (long)N_ * N_,
             qkv + 2 * INNER_, 3 * INNER_, (long)N_ * 3 * INNER_, DHEAD_,
             attnout, INNER_, (long)N_ * INNER_, DHEAD_,
             N_, DHEAD_, N_, 1.f, nullptr, 0, BH);
        // x += out @ Wo_sa[i] + bo_sa[i]
        gemm(false, attnout, INNER_, 0, 0,
             Wo_sa + (size_t)i * INNER_ * DIM_, DIM_, 0, 0,
             xout, DIM_, 0, 0,
             B_ * N_, DIM_, INNER_, 1.f, bo_sa + (size_t)i * DIM_, FLAG_RES, 1);

        // ================= cross-attention =================
        ln_kernel<<<B_ * N_, 256>>>(xout, ln_g + (size_t)(i * 3 + 1) * DIM_,
                                    ln_b + (size_t)(i * 3 + 1) * DIM_, h);
        // kv = context @ Wkv[i]    [8192 x 2048]
        gemm(false, context, CTX_, 0, 0,
             Wkv + (size_t)i * CTX_ * 2 * INNER_, 2 * INNER_, 0, 0,
             kv, 2 * INNER_, 0, 0,
             B_ * M_, 2 * INNER_, CTX_, 1.f, nullptr, 0, 1);
        // q = h @ Wq[i]            [4096 x 1024]
        gemm(false, h, DIM_, 0, 0,
             Wq + (size_t)i * DIM_ * INNER_, INNER_, 0, 0,
             q, INNER_, 0, 0,
             B_ * N_, INNER_, DIM_, 1.f, nullptr, 0, 1);
        // scores = Q K^T * scale   per (b,h): [1024 x 2048]
        gemm(true, q, INNER_, (long)N_ * INNER_, DHEAD_,
             kv, 2 * INNER_, (long)M_ * 2 * INNER_, DHEAD_,
             scores, M_, (long)HEADS_ * N_ * M_, (long)N_ * M_,
             N_, M_, DHEAD_, SCALE_, nullptr, 0, BH);
        // cross-attn mask is a per-row constant shift -> softmax-invariant; skip it
        softmax_kernel<<<BH * N_, 256>>>(scores, M_, HEADS_ * N_, nullptr, 0.f);
        // out = attn @ V           per (b,h): [1024 x 64], K-dim 2048
        gemm(false, scores, M_, (long)HEADS_ * N_ * M_, (long)N_ * M_,
             kv + INNER_, 2 * INNER_, (long)M_ * 2 * INNER_, DHEAD_,
             attnout, INNER_, (long)N_ * INNER_, DHEAD_,
             N_, DHEAD_, M_, 1.f, nullptr, 0, BH);
        // x += out @ Wo_ca[i] + bo_ca[i]
        gemm(false, attnout, INNER_, 0, 0,
             Wo_ca + (size_t)i * INNER_ * DIM_, DIM_, 0, 0,
             xout, DIM_, 0, 0,
             B_ * N_, DIM_, INNER_, 1.f, bo_ca + (size_t)i * DIM_, FLAG_RES, 1);

        // ================= feed-forward =================
        ln_kernel<<<B_ * N_, 256>>>(xout, ln_g + (size_t)(i * 3 + 2) * DIM_,
                                    ln_b + (size_t)(i * 3 + 2) * DIM_, h);
        // ffn = gelu(h @ W1[i] + b1[i])   [4096 x 4096]
        gemm(false, h, DIM_, 0, 0,
             W1 + (size_t)i * DIM_ * MLP_, MLP_, 0, 0,
             ffn, MLP_, 0, 0,
             B_ * N_, MLP_, DIM_, 1.f, b1 + (size_t)i * MLP_, FLAG_GELU, 1);
        // x += ffn @ W2[i] + b2[i]
        gemm(false, ffn, MLP_, 0, 0,
             W2 + (size_t)i * MLP_ * DIM_, DIM_, 0, 0,
             xout, DIM_, 0, 0,
             B_ * N_, DIM_, MLP_, 1.f, b2 + (size_t)i * DIM_, FLAG_RES, 1);
    }
}

// round 3
// speedup vs baseline: 1.1300x; 1.1300x over previous
#include <cuda_runtime.h>
#include <cuda_bf16.h>
#include <mma.h>
#include <math.h>
#include <stdint.h>

using namespace nvcuda;
typedef __nv_bfloat16 bf16;

#define DEPTH_  4
#define DIM_    1024
#define HEADS_  16
#define DHEAD_  64
#define MLP_    4096
#define CTX_    1024
#define INNER_  1024
#define B_      4
#define N_      1024
#define M_      2048
#define SCALE_  0.125f

#define FLAG_RES  1
#define FLAG_GELU 2

// ===================== scratch (device globals; no allocs) =====================
__device__ bf16 g_Wqkv_h [4ul*DIM_*3*INNER_], g_Wqkv_l [4ul*DIM_*3*INNER_];
__device__ bf16 g_Wosa_h [4ul*INNER_*DIM_],   g_Wosa_l [4ul*INNER_*DIM_];
__device__ bf16 g_Wkv_h  [4ul*CTX_*2*INNER_], g_Wkv_l  [4ul*CTX_*2*INNER_];
__device__ bf16 g_Wq_h   [4ul*DIM_*INNER_],   g_Wq_l   [4ul*DIM_*INNER_];
__device__ bf16 g_Woca_h [4ul*INNER_*DIM_],   g_Woca_l [4ul*INNER_*DIM_];
__device__ bf16 g_W1_h   [4ul*DIM_*MLP_],     g_W1_l   [4ul*DIM_*MLP_];
__device__ bf16 g_W2_h   [4ul*MLP_*DIM_],     g_W2_l   [4ul*MLP_*DIM_];
__device__ bf16 g_ctx_h  [(size_t)B_*M_*CTX_],g_ctx_l  [(size_t)B_*M_*CTX_];
__device__ bf16 g_h_h    [(size_t)B_*N_*DIM_],g_h_l    [(size_t)B_*N_*DIM_];
__device__ bf16 g_qkv_h  [(size_t)B_*N_*3*INNER_], g_qkv_l [(size_t)B_*N_*3*INNER_];
__device__ bf16 g_q_h    [(size_t)B_*N_*INNER_],   g_q_l   [(size_t)B_*N_*INNER_];
__device__ bf16 g_kv_h   [(size_t)B_*M_*2*INNER_], g_kv_l  [(size_t)B_*M_*2*INNER_];
__device__ bf16 g_ao_h   [(size_t)B_*N_*INNER_],   g_ao_l  [(size_t)B_*N_*INNER_];
__device__ bf16 g_ffn_h  [(size_t)B_*N_*MLP_],     g_ffn_l [(size_t)B_*N_*MLP_];
__device__ float g_scores[(size_t)B_*HEADS_*N_*M_];
__device__ bf16 g_p_h    [(size_t)B_*HEADS_*N_*M_], g_p_l [(size_t)B_*HEADS_*N_*M_];

// ===================== small helpers =====================
__device__ __forceinline__ float warpSum(float v) {
    #pragma unroll
    for (int o = 16; o; o >>= 1) v += __shfl_xor_sync(0xffffffffu, v, o);
    return v;
}
__device__ __forceinline__ float warpMax(float v) {
    #pragma unroll
    for (int o = 16; o; o >>= 1) v = fmaxf(v, __shfl_xor_sync(0xffffffffu, v, o));
    return v;
}
__device__ __forceinline__ void splt(float v, bf16& h, bf16& l) {
    h = __float2bfloat16(v);
    l = __float2bfloat16(v - __bfloat162float(h));
}

// ===================== fp32 -> (hi, lo) split =====================
__global__ __launch_bounds__(256) void split_kernel(
    const float* __restrict__ s, bf16* __restrict__ hi, bf16* __restrict__ lo, size_t n4)
{
    size_t i = (size_t)blockIdx.x * 256 + threadIdx.x;
    if (i >= n4) return;
    float4 v = ((const float4*)s)[i];
    union { bf16 b[4]; uint2 u; } H, L;
    splt(v.x, H.b[0], L.b[0]); splt(v.y, H.b[1], L.b[1]);
    splt(v.z, H.b[2], L.b[2]); splt(v.w, H.b[3], L.b[3]);
    ((uint2*)hi)[i] = H.u;
    ((uint2*)lo)[i] = L.u;
}

// ===================== LayerNorm -> hi/lo =====================
__global__ __launch_bounds__(256) void ln_split_kernel(
    const float* __restrict__ x, const float* __restrict__ g,
    const float* __restrict__ b, bf16* __restrict__ oh, bf16* __restrict__ ol)
{
    const int row = blockIdx.x;
    const float* xr = x + (size_t)row * DIM_;
    float v[4]; float s = 0.f, ss = 0.f;
    #pragma unroll
    for (int i = 0; i < 4; i++) {
        v[i] = xr[threadIdx.x + i * 256];
        s += v[i]; ss += v[i] * v[i];
    }
    __shared__ float shs[8], shq[8];
    float ws = warpSum(s), wq = warpSum(ss);
    int wid = threadIdx.x >> 5, lane = threadIdx.x & 31;
    if (lane == 0) { shs[wid] = ws; shq[wid] = wq; }
    __syncthreads();
    if (threadIdx.x == 0) {
        float a = 0.f, c = 0.f;
        #pragma unroll
        for (int w = 0; w < 8; w++) { a += shs[w]; c += shq[w]; }
        shs[0] = a; shq[0] = c;
    }
    __syncthreads();
    const float mean = shs[0] * (1.f / DIM_);
    const float var  = shq[0] * (1.f / DIM_) - mean * mean;
    const float rstd = rsqrtf(var + 1e-5f);
    #pragma unroll
    for (int i = 0; i < 4; i++) {
        int c = threadIdx.x + i * 256;
        float y = (v[i] - mean) * rstd * g[c] + b[c];
        bf16 hv, lv; splt(y, hv, lv);
        oh[(size_t)row * DIM_ + c] = hv;
        ol[(size_t)row * DIM_ + c] = lv;
    }
}

// ===================== softmax (scores already scaled) -> hi/lo =====================
__global__ __launch_bounds__(256) void softmax_split_kernel(
    const float* __restrict__ S, int nk, int rows_per_b,
    const int* __restrict__ mask, float mbias,
    bf16* __restrict__ ph, bf16* __restrict__ pl)
{
    const size_t row = blockIdx.x;
    const float* r = S + row * (size_t)nk;
    const int* mrow = mask ? (mask + (size_t)(row / rows_per_b) * nk) : nullptr;
    const int cnt = nk >> 8;

    float v[8]; float mx = -3.4e38f;
    #pragma unroll 8
    for (int i = 0; i < 8; i++) {
        if (i < cnt) {
            int c = (i << 8) + threadIdx.x;
            float val = r[c];
            if (mrow) val -= (1.f - (float)mrow[c]) * mbias;
            v[i] = val; mx = fmaxf(mx, val);
        }
    }
    __shared__ float shm[8], shs[8];
    int wid = threadIdx.x >> 5, lane = threadIdx.x & 31;
    float wm = warpMax(mx);
    if (lane == 0) shm[wid] = wm;
    __syncthreads();
    if (threadIdx.x == 0) {
        float m = shm[0];
        #pragma unroll
        for (int w = 1; w < 8; w++) m = fmaxf(m, shm[w]);
        shm[0] = m;
    }
    __syncthreads();
    mx = shm[0];
    float sum = 0.f;
    #pragma unroll 8
    for (int i = 0; i < 8; i++)
        if (i < cnt) { v[i] = expf(v[i] - mx); sum += v[i]; }
    float wsm = warpSum(sum);
    if (lane == 0) shs[wid] = wsm;
    __syncthreads();
    if (threadIdx.x == 0) {
        float a = 0.f;
        #pragma unroll
        for (int w = 0; w < 8; w++) a += shs[w];
        shs[0] = a;
    }
    __syncthreads();
    const float inv = 1.f / shs[0];
    #pragma unroll 8
    for (int i = 0; i < 8; i++) {
        if (i < cnt) {
            int c = (i << 8) + threadIdx.x;
            bf16 hv, lv; splt(v[i] * inv, hv, lv);
            ph[row * (size_t)nk + c] = hv;
            pl[row * (size_t)nk + c] = lv;
        }
    }
}

// ===================== tensor-core GEMM, 3-term bf16 split =====================
// C = alpha * A * op(B) (+bias)(+gelu)(+residual); A,B given as (hi,lo) pairs.
// op(B)=B [K,N] row-major (TB=false) or B^T with B stored [N,K] (TB=true).
#define BM 128
#define BN 128
#define BK 16

template<bool TB>
__global__ __launch_bounds__(256) void gemm_tc(
    const bf16* __restrict__ Ah, const bf16* __restrict__ Al, int lda, long sAb, long sAh,
    const bf16* __restrict__ Bh, const bf16* __restrict__ Bl, int ldb, long sBb, long sBh,
    float* __restrict__ Cf, bf16* __restrict__ Chi, bf16* __restrict__ Clo,
    int ldc, long sCb, long sCh,
    int Ndim, int Kdim, float alpha, const float* __restrict__ bias, int flags)
{
    __shared__ __align__(16) bf16 sA[BM][BK + 8];
    constexpr int SBR = TB ? BN : BK;
    constexpr int SBC = TB ? (BK + 8) : (BN + 8);
    __shared__ __align__(16) bf16 sB[SBR][SBC];
    __shared__ float slab[8][256];

    const int z = blockIdx.z;
    const long ob = (long)(z >> 4), oh = (long)(z & 15);
    Ah += ob * sAb + oh * sAh;  Al += ob * sAb + oh * sAh;
    Bh += ob * sBb + oh * sBh;  Bl += ob * sBb + oh * sBh;
    const size_t coff = (size_t)(ob * sCb + oh * sCh);

    const int rowBase = blockIdx.y * BM;
    const int colBase = blockIdx.x * BN;
    const int tid = threadIdx.x, wid = tid >> 5, lane = tid & 31;
    const int warpM = wid >> 1, warpN = wid & 1;

    wmma::fragment<wmma::accumulator, 16, 16, 16, float> acc[2][4];
    #pragma unroll
    for (int i = 0; i < 2; i++)
        #pragma unroll
        for (int j = 0; j < 4; j++) wmma::fill_fragment(acc[i][j], 0.f);

    #pragma unroll 1
    for (int seg = 0; seg < 3; seg++) {
        const bf16* Ap = (seg == 2) ? Al : Ah;
        const bf16* Bp = (seg == 1) ? Bl : Bh;
        #pragma unroll 1
        for (int k0 = 0; k0 < Kdim; k0 += BK) {
            {   // A tile: 128x16
                int ar = tid >> 1, ac = (tid & 1) * 8;
                *(uint4*)&sA[ar][ac] =
                    *(const uint4*)(Ap + (size_t)(rowBase + ar) * lda + k0 + ac);
            }
            if (TB) {   // B tile: [n][k] 128x16
                int br = tid >> 1, bc = (tid & 1) * 8;
                *(uint4*)&sB[br][bc] =
                    *(const uint4*)(Bp + (size_t)(colBase + br) * ldb + k0 + bc);
            } else {    // B tile: [k][n] 16x128
                int br = tid >> 4, bc = (tid & 15) * 8;
                int gc = colBase + bc;
                uint4 v = make_uint4(0u, 0u, 0u, 0u);
                if (gc < Ndim)
                    v = *(const uint4*)(Bp + (size_t)(k0 + br) * ldb + gc);
                *(uint4*)&sB[br][bc] = v;
            }
            __syncthreads();

            wmma::fragment<wmma::matrix_a, 16, 16, 16, bf16, wmma::row_major> af[2];
            #pragma unroll
            for (int i = 0; i < 2; i++)
                wmma::load_matrix_sync(af[i], &sA[warpM * 32 + i * 16][0], BK + 8);
            if (TB) {
                wmma::fragment<wmma::matrix_b, 16, 16, 16, bf16, wmma::col_major> bfr;
                #pragma unroll
                for (int j = 0; j < 4; j++) {
                    wmma::load_matrix_sync(bfr, &sB[warpN * 64 + j * 16][0], BK + 8);
                    #pragma unroll
                    for (int i = 0; i < 2; i++)
                        wmma::mma_sync(acc[i][j], af[i], bfr, acc[i][j]);
                }
            } else {
                wmma::fragment<wmma::matrix_b, 16, 16, 16, bf16, wmma::row_major> bfr;
                #pragma unroll
                for (int j = 0; j < 4; j++) {
                    wmma::load_matrix_sync(bfr, &sB[0][warpN * 64 + j * 16], BN + 8);
                    #pragma unroll
                    for (int i = 0; i < 2; i++)
                        wmma::mma_sync(acc[i][j], af[i], bfr, acc[i][j]);
                }
            }
            __syncthreads();
        }
    }

    // -------- fused epilogue --------
    #pragma unroll
    for (int i = 0; i < 2; i++) {
        #pragma unroll
        for (int j = 0; j < 4; j++) {
            wmma::store_matrix_sync(&slab[wid][0], acc[i][j], 16, wmma::mem_row_major);
            __syncwarp();
            int rr = lane >> 1, c0 = (lane & 1) * 8;
            size_t r = (size_t)(rowBase + warpM * 32 + i * 16 + rr);
            int cb = colBase + warpN * 64 + j * 16 + c0;
            #pragma unroll
            for (int u = 0; u < 8; u++) {
                int c = cb + u;
                if (c < Ndim) {
                    float v = alpha * slab[wid][rr * 16 + c0 + u];
                    if (bias) v += bias[c];
                    if (flags & FLAG_GELU)
                        v = 0.5f * v * (1.f + erff(v * 0.70710678118654752f));
                    size_t off = coff + r * (size_t)ldc + c;
                    if (flags & FLAG_RES) v += Cf[off];
                    if (Cf) Cf[off] = v;
                    if (Chi) {
                        bf16 hv, lv; splt(v, hv, lv);
                        Chi[off] = hv; Clo[off] = lv;
                    }
                }
            }
            __syncwarp();
        }
    }
}

// ===================== host helpers =====================
static void split(const float* s, bf16* h, bf16* l, size_t n) {
    size_t n4 = n / 4;
    split_kernel<<<(unsigned)((n4 + 255) / 256), 256>>>(s, h, l, n4);
}
static void gemm(bool tb,
                 const bf16* Ah, const bf16* Al, int lda, long sAb, long sAh,
                 const bf16* Bh, const bf16* Bl, int ldb, long sBb, long sBh,
                 float* Cf, bf16* Chi, bf16* Clo, int ldc, long sCb, long sCh,
                 int M, int N, int K, float alpha, const float* bias, int flags, int batches)
{
    dim3 grid((N + BN - 1) / BN, (M + BM - 1) / BM, batches);
    if (tb)
        gemm_tc<true><<<grid, 256>>>(Ah, Al, lda, sAb, sAh, Bh, Bl, ldb, sBb, sBh,
                                     Cf, Chi, Clo, ldc, sCb, sCh, N, K, alpha, bias, flags);
    else
        gemm_tc<false><<<grid, 256>>>(Ah, Al, lda, sAb, sAh, Bh, Bl, ldb, sBb, sBh,
                                      Cf, Chi, Clo, ldc, sCb, sCh, N, K, alpha, bias, flags);
}

#define SYM(p, s) cudaGetSymbolAddress((void**)&p, s)

extern "C" void kernel_launch(void* const* d_in, const int* in_sizes, int n_in,
                              void* d_out, int out_size)
{
    const float* x       = (const float*)d_in[0];
    const float* context = (const float*)d_in[1];
    const int*   mask    = (const int*)  d_in[2];
    const float* ln_g    = (const float*)d_in[3];
    const float* ln_b    = (const float*)d_in[4];
    const float* Wqkv    = (const float*)d_in[5];
    const float* Wo_sa   = (const float*)d_in[6];
    const float* bo_sa   = (const float*)d_in[7];
    const float* Wkv     = (const float*)d_in[8];
    const float* Wq      = (const float*)d_in[9];
    const float* Wo_ca   = (const float*)d_in[10];
    const float* bo_ca   = (const float*)d_in[11];
    const float* W1      = (const float*)d_in[12];
    const float* b1      = (const float*)d_in[13];
    const float* W2      = (const float*)d_in[14];
    const float* b2      = (const float*)d_in[15];
    float* xout = (float*)d_out;

    bf16 *Wqkv_h,*Wqkv_l,*Wosa_h,*Wosa_l,*Wkv_h,*Wkv_l,*Wq_h,*Wq_l,*Woca_h,*Woca_l;
    bf16 *W1_h,*W1_l,*W2_h,*W2_l,*ctx_h,*ctx_l,*h_h,*h_l,*qkv_h,*qkv_l;
    bf16 *q_h,*q_l,*kv_h,*kv_l,*ao_h,*ao_l,*ffn_h,*ffn_l,*p_h,*p_l;
    float* scores;
    SYM(Wqkv_h,g_Wqkv_h); SYM(Wqkv_l,g_Wqkv_l); SYM(Wosa_h,g_Wosa_h); SYM(Wosa_l,g_Wosa_l);
    SYM(Wkv_h,g_Wkv_h);   SYM(Wkv_l,g_Wkv_l);   SYM(Wq_h,g_Wq_h);     SYM(Wq_l,g_Wq_l);
    SYM(Woca_h,g_Woca_h); SYM(Woca_l,g_Woca_l); SYM(W1_h,g_W1_h);     SYM(W1_l,g_W1_l);
    SYM(W2_h,g_W2_h);     SYM(W2_l,g_W2_l);     SYM(ctx_h,g_ctx_h);   SYM(ctx_l,g_ctx_l);
    SYM(h_h,g_h_h);       SYM(h_l,g_h_l);       SYM(qkv_h,g_qkv_h);   SYM(qkv_l,g_qkv_l);
    SYM(q_h,g_q_h);       SYM(q_l,g_q_l);       SYM(kv_h,g_kv_h);     SYM(kv_l,g_kv_l);
    SYM(ao_h,g_ao_h);     SYM(ao_l,g_ao_l);     SYM(ffn_h,g_ffn_h);   SYM(ffn_l,g_ffn_l);
    SYM(p_h,g_p_h);       SYM(p_l,g_p_l);       SYM(scores,g_scores);

    // residual stream lives in d_out
    cudaMemcpyAsync(xout, x, sizeof(float) * B_ * N_ * DIM_, cudaMemcpyDeviceToDevice, 0);

    // split weights + context once per call
    split(Wqkv,  Wqkv_h, Wqkv_l, 4ul*DIM_*3*INNER_);
    split(Wo_sa, Wosa_h, Wosa_l, 4ul*INNER_*DIM_);
    split(Wkv,   Wkv_h,  Wkv_l,  4ul*CTX_*2*INNER_);
    split(Wq,    Wq_h,   Wq_l,   4ul*DIM_*INNER_);
    split(Wo_ca, Woca_h, Woca_l, 4ul*INNER_*DIM_);
    split(W1,    W1_h,   W1_l,   4ul*DIM_*MLP_);
    split(W2,    W2_h,   W2_l,   4ul*MLP_*DIM_);
    split(context, ctx_h, ctx_l, (size_t)B_*M_*CTX_);

    const int BH = B_ * HEADS_;

    for (int i = 0; i < DEPTH_; i++) {
        // ---------------- self-attention ----------------
        ln_split_kernel<<<B_*N_, 256>>>(xout, ln_g + (size_t)(i*3+0)*DIM_,
                                        ln_b + (size_t)(i*3+0)*DIM_, h_h, h_l);
        // qkv = h @ Wqkv[i]  -> hi/lo
        gemm(false, h_h, h_l, DIM_, 0, 0,
             Wqkv_h + (size_t)i*DIM_*3*INNER_, Wqkv_l + (size_t)i*DIM_*3*INNER_,
             3*INNER_, 0, 0,
             nullptr, qkv_h, qkv_l, 3*INNER_, 0, 0,
             B_*N_, 3*INNER_, DIM_, 1.f, nullptr, 0, 1);
        // scores = (Q K^T) * SCALE    per (b,h)
        gemm(true, qkv_h, qkv_l, 3*INNER_, (long)N_*3*INNER_, DHEAD_,
             qkv_h + INNER_, qkv_l + INNER_, 3*INNER_, (long)N_*3*INNER_, DHEAD_,
             scores, nullptr, nullptr, N_, (long)HEADS_*N_*N_, (long)N_*N_,
             N_, N_, DHEAD_, SCALE_, nullptr, 0, BH);
        softmax_split_kernel<<<BH*N_, 256>>>(scores, N_, HEADS_*N_, mask, 1e11f, p_h, p_l);
        // ao = P @ V
        gemm(false, p_h, p_l, N_, (long)HEADS_*N_*N_, (long)N_*N_,
             qkv_h + 2*INNER_, qkv_l + 2*INNER_, 3*INNER_, (long)N_*3*INNER_, DHEAD_,
             nullptr, ao_h, ao_l, INNER_, (long)N_*INNER_, DHEAD_,
             N_, DHEAD_, N_, 1.f, nullptr, 0, BH);
        // x += ao @ Wo_sa + bo_sa
        gemm(false, ao_h, ao_l, INNER_, 0, 0,
             Wosa_h + (size_t)i*INNER_*DIM_, Wosa_l + (size_t)i*INNER_*DIM_, DIM_, 0, 0,
             xout, nullptr, nullptr, DIM_, 0, 0,
             B_*N_, DIM_, INNER_, 1.f, bo_sa + (size_t)i*DIM_, FLAG_RES, 1);

        // ---------------- cross-attention ----------------
        ln_split_kernel<<<B_*N_, 256>>>(xout, ln_g + (size_t)(i*3+1)*DIM_,
                                        ln_b + (size_t)(i*3+1)*DIM_, h_h, h_l);
        gemm(false, ctx_h, ctx_l, CTX_, 0, 0,
             Wkv_h + (size_t)i*CTX_*2*INNER_, Wkv_l + (size_t)i*CTX_*2*INNER_,
             2*INNER_, 0, 0,
             nullptr, kv_h, kv_l, 2*INNER_, 0, 0,
             B_*M_, 2*INNER_, CTX_, 1.f, nullptr, 0, 1);
        gemm(false, h_h, h_l, DIM_, 0, 0,
             Wq_h + (size_t)i*DIM_*INNER_, Wq_l + (size_t)i*DIM_*INNER_, INNER_, 0, 0,
             nullptr, q_h, q_l, INNER_, 0, 0,
             B_*N_, INNER_, DIM_, 1.f, nullptr, 0, 1);
        gemm(true, q_h, q_l, INNER_, (long)N_*INNER_, DHEAD_,
             kv_h, kv_l, 2*INNER_, (long)M_*2*INNER_, DHEAD_,
             scores, nullptr, nullptr, M_, (long)HEADS_*N_*M_, (long)N_*M_,
             N_, M_, DHEAD_, SCALE_, nullptr, 0, BH);
        // per-row-constant query mask is softmax-invariant; skip it
        softmax_split_kernel<<<BH*N_, 256>>>(scores, M_, HEADS_*N_, nullptr, 0.f, p_h, p_l);
        gemm(false, p_h, p_l, M_, (long)HEADS_*N_*M_, (long)N_*M_,
             kv_h + INNER_, kv_l + INNER_, 2*INNER_, (long)M_*2*INNER_, DHEAD_,
             nullptr, ao_h, ao_l, INNER_, (long)N_*INNER_, DHEAD_,
             N_, DHEAD_, M_, 1.f, nullptr, 0, BH);
        gemm(false, ao_h, ao_l, INNER_, 0, 0,
             Woca_h + (size_t)i*INNER_*DIM_, Woca_l + (size_t)i*INNER_*DIM_, DIM_, 0, 0,
             xout, nullptr, nullptr, DIM_, 0, 0,
             B_*N_, DIM_, INNER_, 1.f, bo_ca + (size_t)i*DIM_, FLAG_RES, 1);

        // ---------------- feed-forward ----------------
        ln_split_kernel<<<B_*N_, 256>>>(xout, ln_g + (size_t)(i*3+2)*DIM_,
                                        ln_b + (size_t)(i*3+2)*DIM_, h_h, h_l);
        gemm(false, h_h, h_l, DIM_, 0, 0,
             W1_h + (size_t)i*DIM_*MLP_, W1_l + (size_t)i*DIM_*MLP_, MLP_, 0, 0,
             nullptr, ffn_h, ffn_l, MLP_, 0, 0,
             B_*N_, MLP_, DIM_, 1.f, b1 + (size_t)i*MLP_, FLAG_GELU, 1);
        gemm(false, ffn_h, ffn_l, MLP_, 0, 0,
             W2_h + (size_t)i*MLP_*DIM_, W2_l + (size_t)i*MLP_*DIM_, DIM_, 0, 0,
             xout, nullptr, nullptr, DIM_, 0, 0,
             B_*N_, DIM_, MLP_, 1.f, b2 + (size_t)i*DIM_, FLAG_RES, 1);
    }
}